// round 3
// baseline (speedup 1.0000x reference)
#include <cuda_runtime.h>
#include <cuda_bf16.h>

#define N_NODES 100000
#define N_EDGES 1600000
#define C 64
#define G 8            // nodes per warp in the fused kernel

__device__ int g_row_ptr[N_NODES + 1];

#define FMA2(acc, a, b) asm("fma.rn.f32x2 %0, %1, %2, %0;" : "+l"(acc) : "l"(a), "l"(b))
#define ADD2(d, a, b)   asm("add.rn.f32x2 %0, %1, %2;" : "=l"(d) : "l"(a), "l"(b))

static __device__ __forceinline__ unsigned long long dup_f32x2(float x) {
    unsigned long long r;
    asm("mov.b64 %0, {%1, %1};" : "=l"(r) : "f"(x));
    return r;
}
static __device__ __forceinline__ float2 unpack_f32x2(unsigned long long v) {
    float2 r;
    asm("mov.b64 {%0, %1}, %2;" : "=f"(r.x), "=f"(r.y) : "l"(v));
    return r;
}
static __device__ __forceinline__ unsigned long long pack_f32x2(float x, float y) {
    unsigned long long r;
    asm("mov.b64 %0, {%1, %2};" : "=l"(r) : "f"(x), "f"(y));
    return r;
}

// ---------------------------------------------------------------------------
// Kernel 1: CSR row pointers by linear interval fill (row_index is sorted).
// row_ptr[n] = lower_bound(row_index, n). Thread e fills (row[e-1], row[e]].
// ---------------------------------------------------------------------------
__global__ __launch_bounds__(256) void rowptr_fill_kernel(const int* __restrict__ row_index) {
    int e = blockIdx.x * blockDim.x + threadIdx.x;
    if (e >= N_EDGES) return;
    int cur = __ldg(&row_index[e]);
    if (e == 0) {
        for (int n = 0; n <= cur; n++) g_row_ptr[n] = 0;
    } else {
        int prev = __ldg(&row_index[e - 1]);
        for (int n = prev + 1; n <= cur; n++) g_row_ptr[n] = e;
    }
    if (e == N_EDGES - 1) {
        for (int n = cur + 1; n <= N_NODES; n++) g_row_ptr[n] = N_EDGES;
    }
}

// ---------------------------------------------------------------------------
// Kernel 2 (fused): per-node segment-sum of gathered x rows, then the 64x64
// weight transform done in-register (lane l holds W[:, 2l:2l+2] = 64 f32x2),
// degree scale + bias, store. One warp handles G consecutive nodes.
// Aggregated row is redistributed via a 512B smem stage per warp.
// ---------------------------------------------------------------------------
__global__ __launch_bounds__(128, 3) void fused_gcn_kernel(
    const float* __restrict__ x,
    const float* __restrict__ w,
    const float* __restrict__ bias,
    const int* __restrict__ column_index,
    const float* __restrict__ degrees,
    float* __restrict__ out)
{
    __shared__ float2 sbuf[4][32];

    const int tid = threadIdx.x;
    const int wip = tid >> 5;
    const int lane = tid & 31;

    // W columns (2*lane, 2*lane+1) packed into 64 f32x2 registers.
    unsigned long long wreg[64];
#pragma unroll
    for (int k = 0; k < 64; k++) {
        float2 wv = __ldg((const float2*)(w + k * 64) + lane);
        wreg[k] = pack_f32x2(wv.x, wv.y);
    }
    const float2 b = __ldg((const float2*)bias + lane);

    const int gwarp = blockIdx.x * 4 + wip;
    const int node0 = gwarp * G;

    for (int g = 0; g < G; g++) {
        const int node = node0 + g;
        if (node >= N_NODES) return;

        const int start = g_row_ptr[node];
        const int end = g_row_ptr[node + 1];

        // --- gather + segment sum of x rows (lane owns feature cols 2l,2l+1)
        float ax = 0.f, ay = 0.f;
        int e = start;
        for (; e + 3 < end; e += 4) {
            int s0 = __ldg(&column_index[e]);
            int s1 = __ldg(&column_index[e + 1]);
            int s2 = __ldg(&column_index[e + 2]);
            int s3 = __ldg(&column_index[e + 3]);
            float2 v0 = __ldg((const float2*)(x + (size_t)s0 * C) + lane);
            float2 v1 = __ldg((const float2*)(x + (size_t)s1 * C) + lane);
            float2 v2 = __ldg((const float2*)(x + (size_t)s2 * C) + lane);
            float2 v3 = __ldg((const float2*)(x + (size_t)s3 * C) + lane);
            ax += (v0.x + v1.x) + (v2.x + v3.x);
            ay += (v0.y + v1.y) + (v2.y + v3.y);
        }
        for (; e < end; e++) {
            int s0 = __ldg(&column_index[e]);
            float2 v0 = __ldg((const float2*)(x + (size_t)s0 * C) + lane);
            ax += v0.x;
            ay += v0.y;
        }

        // --- redistribute aggregated row via smem (broadcast reads)
        sbuf[wip][lane] = make_float2(ax, ay);
        __syncwarp();

        // --- in-register GEMV: acc[0..1] = agg_row @ W[:, 2l:2l+2]
        unsigned long long a0 = 0ull, a1 = 0ull, a2 = 0ull, a3 = 0ull;
        const float4* ag = (const float4*)&sbuf[wip][0];
#pragma unroll
        for (int k4 = 0; k4 < 16; k4++) {
            float4 a = ag[k4];   // broadcast LDS.128: agg[4k..4k+3]
            FMA2(a0, dup_f32x2(a.x), wreg[4 * k4 + 0]);
            FMA2(a1, dup_f32x2(a.y), wreg[4 * k4 + 1]);
            FMA2(a2, dup_f32x2(a.z), wreg[4 * k4 + 2]);
            FMA2(a3, dup_f32x2(a.w), wreg[4 * k4 + 3]);
        }
        __syncwarp();   // sbuf reused next g-iteration

        unsigned long long s01, s23, stot;
        ADD2(s01, a0, a1);
        ADD2(s23, a2, a3);
        ADD2(stot, s01, s23);
        float2 av = unpack_f32x2(stot);

        const float d = __ldg(&degrees[node]);
        float2 o;
        o.x = av.x * d + b.x;
        o.y = av.y * d + b.y;
        ((float2*)(out + (size_t)node * C))[lane] = o;
    }
}

// ---------------------------------------------------------------------------
extern "C" void kernel_launch(void* const* d_in, const int* in_sizes, int n_in,
                              void* d_out, int out_size) {
    const float* x            = (const float*)d_in[0];   // [N_NODES, 64]
    const float* weight       = (const float*)d_in[1];   // [64, 64]
    const float* bias         = (const float*)d_in[2];   // [64]
    const int*   column_index = (const int*)d_in[3];     // [N_EDGES]
    const int*   row_index    = (const int*)d_in[4];     // [N_EDGES] sorted
    const float* degrees      = (const float*)d_in[5];   // [N_NODES]
    float* out = (float*)d_out;                          // [N_NODES, 64]

    // 1) CSR row pointers via linear interval fill
    rowptr_fill_kernel<<<(N_EDGES + 255) / 256, 256>>>(row_index);

    // 2) fused gather + segment-sum + (aggÂ·W) + degree scale + bias
    const int warps = (N_NODES + G - 1) / G;
    const int blocks = (warps + 3) / 4;
    fused_gcn_kernel<<<blocks, 128>>>(x, weight, bias, column_index, degrees, out);
}

// round 4
// speedup vs baseline: 1.5705x; 1.5705x over previous
#include <cuda_runtime.h>
#include <cuda_bf16.h>

#define N_NODES 100000
#define N_EDGES 1600000
#define C 64

// Scratch: transformed features h = x @ W, and CSR row pointers.
__device__ float g_h[(size_t)N_NODES * C];
__device__ int g_row_ptr[N_NODES + 1];

static __device__ __forceinline__ unsigned long long dup_f32x2(float x) {
    unsigned long long r;
    asm("mov.b64 %0, {%1, %1};" : "=l"(r) : "f"(x));
    return r;
}
static __device__ __forceinline__ float2 unpack_f32x2(unsigned long long v) {
    float2 r;
    asm("mov.b64 {%0, %1}, %2;" : "=f"(r.x), "=f"(r.y) : "l"(v));
    return r;
}
#define FMA2(acc, a, b) asm("fma.rn.f32x2 %0, %1, %2, %0;" : "+l"(acc) : "l"(a), "l"(b))

// ---------------------------------------------------------------------------
// Kernel 1: CSR row pointers by linear interval fill (row_index is sorted).
// row_ptr[n] = lower_bound(row_index, n). Thread e fills (row[e-1], row[e]].
// ---------------------------------------------------------------------------
__global__ __launch_bounds__(256) void rowptr_fill_kernel(const int* __restrict__ row_index) {
    int e = blockIdx.x * blockDim.x + threadIdx.x;
    if (e >= N_EDGES) return;
    int cur = __ldg(&row_index[e]);
    if (e == 0) {
        for (int n = 0; n <= cur; n++) g_row_ptr[n] = 0;
    } else {
        int prev = __ldg(&row_index[e - 1]);
        for (int n = prev + 1; n <= cur; n++) g_row_ptr[n] = e;
    }
    if (e == N_EDGES - 1) {
        for (int n = cur + 1; n <= N_NODES; n++) g_row_ptr[n] = N_EDGES;
    }
}

// ---------------------------------------------------------------------------
// Kernel 2: h = x @ W
// 128 rows per block, 128 threads. Thread (warp w, lane l) computes rows
// {l, l+32, l+64, l+96} x cols [w*16, w*16+16) in 32 packed f32x2 accumulators.
// Per k: 4 broadcast LDS.128 (W) + 4 conflict-free LDS (x) feed 32 FFMA2.
// ---------------------------------------------------------------------------
__global__ __launch_bounds__(128) void gemm_kernel(const float* __restrict__ x,
                                                   const float* __restrict__ w) {
    __shared__ float ws[64 * 64];    // 16 KB, W row-major [k][n]
    __shared__ float xs[128 * 64];   // 32 KB, XOR-swizzled x tile (row-major)

    const int tid = threadIdx.x;
    const int w_id = tid >> 5;       // warp -> 16-col slice
    const int l = tid & 31;          // lane -> row set
    const long row0 = (long)blockIdx.x * 128;

    // Load W (1024 float4) cooperatively.
    const float4* w4 = (const float4*)w;
    float4* ws4 = (float4*)ws;
#pragma unroll
    for (int i = 0; i < 8; i++) ws4[tid + i * 128] = w4[tid + i * 128];

    // Load x tile: 2048 float4 coalesced, scalar XOR-swizzled stores.
#pragma unroll
    for (int i = 0; i < 16; i++) {
        int f4 = i * 128 + tid;
        int r = f4 >> 4, c4 = f4 & 15;
        long gr = row0 + r;
        float4 v = make_float4(0.f, 0.f, 0.f, 0.f);
        if (gr < N_NODES) v = ((const float4*)x)[gr * 16 + c4];
        int sw = r & 31;
        float* base = xs + r * 64;
        base[(c4 * 4 + 0) ^ sw] = v.x;
        base[(c4 * 4 + 1) ^ sw] = v.y;
        base[(c4 * 4 + 2) ^ sw] = v.z;
        base[(c4 * 4 + 3) ^ sw] = v.w;
    }
    __syncthreads();

    unsigned long long acc[4][8];
#pragma unroll
    for (int m = 0; m < 4; m++)
#pragma unroll
        for (int j = 0; j < 8; j++) acc[m][j] = 0ull;

#pragma unroll 4
    for (int k = 0; k < 64; k++) {
        unsigned long long x2[4];
#pragma unroll
        for (int m = 0; m < 4; m++)
            x2[m] = dup_f32x2(xs[(m * 32 + l) * 64 + (k ^ l)]);

        const ulonglong2* wr = (const ulonglong2*)(ws + k * 64 + w_id * 16);
        ulonglong2 wv0 = wr[0], wv1 = wr[1], wv2 = wr[2], wv3 = wr[3];

#pragma unroll
        for (int m = 0; m < 4; m++) {
            FMA2(acc[m][0], x2[m], wv0.x);
            FMA2(acc[m][1], x2[m], wv0.y);
            FMA2(acc[m][2], x2[m], wv1.x);
            FMA2(acc[m][3], x2[m], wv1.y);
            FMA2(acc[m][4], x2[m], wv2.x);
            FMA2(acc[m][5], x2[m], wv2.y);
            FMA2(acc[m][6], x2[m], wv3.x);
            FMA2(acc[m][7], x2[m], wv3.y);
        }
    }

    // Epilogue: stage through smem (reuse xs) so the global store is coalesced.
    __syncthreads();
    float4* xs4 = (float4*)xs;
#pragma unroll
    for (int m = 0; m < 4; m++) {
        int row = m * 32 + l;
        int rsw = row & 15;
#pragma unroll
        for (int j4 = 0; j4 < 4; j4++) {
            float2 a = unpack_f32x2(acc[m][2 * j4]);
            float2 b = unpack_f32x2(acc[m][2 * j4 + 1]);
            xs4[row * 16 + ((w_id * 4 + j4) ^ rsw)] = make_float4(a.x, a.y, b.x, b.y);
        }
    }
    __syncthreads();
#pragma unroll
    for (int i = 0; i < 16; i++) {
        int f4 = i * 128 + tid;
        int row = f4 >> 4, c4 = f4 & 15;
        long gr = row0 + row;
        if (gr < N_NODES)
            ((float4*)g_h)[gr * 16 + c4] = xs4[row * 16 + (c4 ^ (row & 15))];
    }
}

// ---------------------------------------------------------------------------
// Kernel 3: warp-per-node segment sum over gathered h rows, fused
// degree scale + bias. No atomics (CSR segments). float2 per lane.
// Low register count + full occupancy = gather MLP.
// ---------------------------------------------------------------------------
__global__ __launch_bounds__(256) void agg_kernel(const int* __restrict__ column_index,
                                                  const float* __restrict__ degrees,
                                                  const float* __restrict__ bias,
                                                  float* __restrict__ out) {
    const int gwarp = (blockIdx.x * blockDim.x + threadIdx.x) >> 5;
    const int lane = threadIdx.x & 31;
    if (gwarp >= N_NODES) return;

    const int start = g_row_ptr[gwarp];
    const int end = g_row_ptr[gwarp + 1];

    float ax = 0.f, ay = 0.f;

    int e = start;
    for (; e + 3 < end; e += 4) {
        int s0 = __ldg(&column_index[e]);
        int s1 = __ldg(&column_index[e + 1]);
        int s2 = __ldg(&column_index[e + 2]);
        int s3 = __ldg(&column_index[e + 3]);
        float2 v0 = __ldg((const float2*)(g_h + (size_t)s0 * C) + lane);
        float2 v1 = __ldg((const float2*)(g_h + (size_t)s1 * C) + lane);
        float2 v2 = __ldg((const float2*)(g_h + (size_t)s2 * C) + lane);
        float2 v3 = __ldg((const float2*)(g_h + (size_t)s3 * C) + lane);
        ax += (v0.x + v1.x) + (v2.x + v3.x);
        ay += (v0.y + v1.y) + (v2.y + v3.y);
    }
    for (; e < end; e++) {
        int s0 = __ldg(&column_index[e]);
        float2 v0 = __ldg((const float2*)(g_h + (size_t)s0 * C) + lane);
        ax += v0.x;
        ay += v0.y;
    }

    const float d = __ldg(&degrees[gwarp]);
    const float2 b = __ldg((const float2*)bias + lane);
    float2 o;
    o.x = ax * d + b.x;
    o.y = ay * d + b.y;
    ((float2*)(out + (size_t)gwarp * C))[lane] = o;
}

// ---------------------------------------------------------------------------
extern "C" void kernel_launch(void* const* d_in, const int* in_sizes, int n_in,
                              void* d_out, int out_size) {
    const float* x            = (const float*)d_in[0];   // [N_NODES, 64]
    const float* weight       = (const float*)d_in[1];   // [64, 64]
    const float* bias         = (const float*)d_in[2];   // [64]
    const int*   column_index = (const int*)d_in[3];     // [N_EDGES]
    const int*   row_index    = (const int*)d_in[4];     // [N_EDGES] sorted
    const float* degrees      = (const float*)d_in[5];   // [N_NODES]
    float* out = (float*)d_out;                          // [N_NODES, 64]

    // 1) CSR row pointers via linear interval fill (fast, coalesced)
    rowptr_fill_kernel<<<(N_EDGES + 255) / 256, 256>>>(row_index);

    // 2) h = x @ W
    gemm_kernel<<<(N_NODES + 127) / 128, 128>>>(x, weight);

    // 3) gather + segment-sum + degree*agg + bias
    agg_kernel<<<(N_NODES * 32 + 255) / 256, 256>>>(column_index, degrees, bias, out);
}

// round 5
// speedup vs baseline: 1.7059x; 1.0862x over previous
#include <cuda_runtime.h>
#include <cuda_bf16.h>

#define N_NODES 100000
#define N_EDGES 1600000
#define C 64

// Scratch: transformed features h = x @ W, and CSR row pointers.
__device__ float g_h[(size_t)N_NODES * C];
__device__ int g_row_ptr[N_NODES + 1];

static __device__ __forceinline__ unsigned long long dup_f32x2(float x) {
    unsigned long long r;
    asm("mov.b64 %0, {%1, %1};" : "=l"(r) : "f"(x));
    return r;
}
static __device__ __forceinline__ float2 unpack_f32x2(unsigned long long v) {
    float2 r;
    asm("mov.b64 {%0, %1}, %2;" : "=f"(r.x), "=f"(r.y) : "l"(v));
    return r;
}
#define FMA2(acc, a, b) asm("fma.rn.f32x2 %0, %1, %2, %0;" : "+l"(acc) : "l"(a), "l"(b))

// ---------------------------------------------------------------------------
// Kernel 1: CSR row pointers, 8 edges per thread (row_index sorted).
// Two int4 loads + one scalar prev load; fill (prev, cur] intervals.
// ---------------------------------------------------------------------------
__global__ __launch_bounds__(256) void rowptr_fill_kernel(const int* __restrict__ row_index) {
    const int t = blockIdx.x * blockDim.x + threadIdx.x;
    const int NT = N_EDGES / 8;                 // 200000 (N_EDGES % 8 == 0)
    if (t >= NT) return;

    const int4* r4 = (const int4*)row_index;
    int4 a = __ldg(&r4[2 * t]);
    int4 b = __ldg(&r4[2 * t + 1]);
    int vals[8] = {a.x, a.y, a.z, a.w, b.x, b.y, b.z, b.w};

    int prev = (t == 0) ? -1 : __ldg(&row_index[8 * t - 1]);
    const int ebase = 8 * t;
#pragma unroll
    for (int i = 0; i < 8; i++) {
        int cur = vals[i];
        for (int n = prev + 1; n <= cur; n++) g_row_ptr[n] = ebase + i;
        prev = cur;
    }
    if (t == NT - 1) {
        for (int n = prev + 1; n <= N_NODES; n++) g_row_ptr[n] = N_EDGES;
    }
}

// ---------------------------------------------------------------------------
// Kernel 2: h = x @ W  (unchanged from R2/R4 — proven)
// ---------------------------------------------------------------------------
__global__ __launch_bounds__(128) void gemm_kernel(const float* __restrict__ x,
                                                   const float* __restrict__ w) {
    __shared__ float ws[64 * 64];    // 16 KB, W row-major [k][n]
    __shared__ float xs[128 * 64];   // 32 KB, XOR-swizzled x tile (row-major)

    const int tid = threadIdx.x;
    const int w_id = tid >> 5;
    const int l = tid & 31;
    const long row0 = (long)blockIdx.x * 128;

    const float4* w4 = (const float4*)w;
    float4* ws4 = (float4*)ws;
#pragma unroll
    for (int i = 0; i < 8; i++) ws4[tid + i * 128] = w4[tid + i * 128];

#pragma unroll
    for (int i = 0; i < 16; i++) {
        int f4 = i * 128 + tid;
        int r = f4 >> 4, c4 = f4 & 15;
        long gr = row0 + r;
        float4 v = make_float4(0.f, 0.f, 0.f, 0.f);
        if (gr < N_NODES) v = ((const float4*)x)[gr * 16 + c4];
        int sw = r & 31;
        float* base = xs + r * 64;
        base[(c4 * 4 + 0) ^ sw] = v.x;
        base[(c4 * 4 + 1) ^ sw] = v.y;
        base[(c4 * 4 + 2) ^ sw] = v.z;
        base[(c4 * 4 + 3) ^ sw] = v.w;
    }
    __syncthreads();

    unsigned long long acc[4][8];
#pragma unroll
    for (int m = 0; m < 4; m++)
#pragma unroll
        for (int j = 0; j < 8; j++) acc[m][j] = 0ull;

#pragma unroll 4
    for (int k = 0; k < 64; k++) {
        unsigned long long x2[4];
#pragma unroll
        for (int m = 0; m < 4; m++)
            x2[m] = dup_f32x2(xs[(m * 32 + l) * 64 + (k ^ l)]);

        const ulonglong2* wr = (const ulonglong2*)(ws + k * 64 + w_id * 16);
        ulonglong2 wv0 = wr[0], wv1 = wr[1], wv2 = wr[2], wv3 = wr[3];

#pragma unroll
        for (int m = 0; m < 4; m++) {
            FMA2(acc[m][0], x2[m], wv0.x);
            FMA2(acc[m][1], x2[m], wv0.y);
            FMA2(acc[m][2], x2[m], wv1.x);
            FMA2(acc[m][3], x2[m], wv1.y);
            FMA2(acc[m][4], x2[m], wv2.x);
            FMA2(acc[m][5], x2[m], wv2.y);
            FMA2(acc[m][6], x2[m], wv3.x);
            FMA2(acc[m][7], x2[m], wv3.y);
        }
    }

    __syncthreads();
    float4* xs4 = (float4*)xs;
#pragma unroll
    for (int m = 0; m < 4; m++) {
        int row = m * 32 + l;
        int rsw = row & 15;
#pragma unroll
        for (int j4 = 0; j4 < 4; j4++) {
            float2 a = unpack_f32x2(acc[m][2 * j4]);
            float2 b = unpack_f32x2(acc[m][2 * j4 + 1]);
            xs4[row * 16 + ((w_id * 4 + j4) ^ rsw)] = make_float4(a.x, a.y, b.x, b.y);
        }
    }
    __syncthreads();
#pragma unroll
    for (int i = 0; i < 16; i++) {
        int f4 = i * 128 + tid;
        int row = f4 >> 4, c4 = f4 & 15;
        long gr = row0 + row;
        if (gr < N_NODES)
            ((float4*)g_h)[gr * 16 + c4] = xs4[row * 16 + (c4 ^ (row & 15))];
    }
}

// ---------------------------------------------------------------------------
// Kernel 3: segment sum, 16 lanes per node (float4 per lane), 2 nodes/warp.
// Fused degree scale + bias. No atomics. Low regs -> full occupancy + MLP.
// ---------------------------------------------------------------------------
__global__ __launch_bounds__(256) void agg_kernel(const int* __restrict__ column_index,
                                                  const float* __restrict__ degrees,
                                                  const float* __restrict__ bias,
                                                  float* __restrict__ out) {
    const int warp = (blockIdx.x * blockDim.x + threadIdx.x) >> 5;
    const int lane = threadIdx.x & 31;
    const int half = lane >> 4;       // which node of the pair
    const int hl = lane & 15;         // float4 slot within the 64-col row
    const int node = warp * 2 + half;
    if (node >= N_NODES) return;

    const int start = g_row_ptr[node];
    const int end = g_row_ptr[node + 1];

    float ax = 0.f, ay = 0.f, az = 0.f, aw = 0.f;

    int e = start;
    for (; e + 3 < end; e += 4) {
        int s0 = __ldg(&column_index[e]);
        int s1 = __ldg(&column_index[e + 1]);
        int s2 = __ldg(&column_index[e + 2]);
        int s3 = __ldg(&column_index[e + 3]);
        float4 v0 = __ldg((const float4*)(g_h + (size_t)s0 * C) + hl);
        float4 v1 = __ldg((const float4*)(g_h + (size_t)s1 * C) + hl);
        float4 v2 = __ldg((const float4*)(g_h + (size_t)s2 * C) + hl);
        float4 v3 = __ldg((const float4*)(g_h + (size_t)s3 * C) + hl);
        ax += (v0.x + v1.x) + (v2.x + v3.x);
        ay += (v0.y + v1.y) + (v2.y + v3.y);
        az += (v0.z + v1.z) + (v2.z + v3.z);
        aw += (v0.w + v1.w) + (v2.w + v3.w);
    }
    for (; e < end; e++) {
        int s0 = __ldg(&column_index[e]);
        float4 v0 = __ldg((const float4*)(g_h + (size_t)s0 * C) + hl);
        ax += v0.x; ay += v0.y; az += v0.z; aw += v0.w;
    }

    const float d = __ldg(&degrees[node]);
    const float4 b = __ldg((const float4*)bias + hl);
    float4 o;
    o.x = ax * d + b.x;
    o.y = ay * d + b.y;
    o.z = az * d + b.z;
    o.w = aw * d + b.w;
    ((float4*)(out + (size_t)node * C))[hl] = o;
}

// ---------------------------------------------------------------------------
extern "C" void kernel_launch(void* const* d_in, const int* in_sizes, int n_in,
                              void* d_out, int out_size) {
    const float* x            = (const float*)d_in[0];   // [N_NODES, 64]
    const float* weight       = (const float*)d_in[1];   // [64, 64]
    const float* bias         = (const float*)d_in[2];   // [64]
    const int*   column_index = (const int*)d_in[3];     // [N_EDGES]
    const int*   row_index    = (const int*)d_in[4];     // [N_EDGES] sorted
    const float* degrees      = (const float*)d_in[5];   // [N_NODES]
    float* out = (float*)d_out;                          // [N_NODES, 64]

    // 1) CSR row pointers: 8 edges/thread interval fill
    const int nt = N_EDGES / 8;
    rowptr_fill_kernel<<<(nt + 255) / 256, 256>>>(row_index);

    // 2) h = x @ W
    gemm_kernel<<<(N_NODES + 127) / 128, 128>>>(x, weight);

    // 3) gather + segment-sum + degree*agg + bias  (2 nodes per warp)
    const int warps = (N_NODES + 1) / 2;
    agg_kernel<<<(warps * 32 + 255) / 256, 256>>>(column_index, degrees, bias, out);
}

// round 6
// speedup vs baseline: 1.7658x; 1.0351x over previous
#include <cuda_runtime.h>
#include <cuda_bf16.h>

#define N_NODES 100000
#define N_EDGES 1600000
#define C 64

// Scratch: aggregated features agg = segment_sum(x[col]), and CSR row ptrs.
__device__ float g_agg[(size_t)N_NODES * C];
__device__ int g_row_ptr[N_NODES + 1];

static __device__ __forceinline__ unsigned long long dup_f32x2(float x) {
    unsigned long long r;
    asm("mov.b64 %0, {%1, %1};" : "=l"(r) : "f"(x));
    return r;
}
static __device__ __forceinline__ float2 unpack_f32x2(unsigned long long v) {
    float2 r;
    asm("mov.b64 {%0, %1}, %2;" : "=f"(r.x), "=f"(r.y) : "l"(v));
    return r;
}
static __device__ __forceinline__ unsigned long long pack_f32x2(float x, float y) {
    unsigned long long r;
    asm("mov.b64 %0, {%1, %2};" : "=l"(r) : "f"(x), "f"(y));
    return r;
}
#define FMA2(acc, a, b) asm("fma.rn.f32x2 %0, %1, %2, %0;" : "+l"(acc) : "l"(a), "l"(b))

// ---------------------------------------------------------------------------
// Kernel 1: CSR row pointers, 8 edges/thread, fast-skip when the window
// contains no row boundary (~61% of threads).
// ---------------------------------------------------------------------------
__global__ __launch_bounds__(256) void rowptr_fill_kernel(const int* __restrict__ row_index) {
    const int t = blockIdx.x * blockDim.x + threadIdx.x;
    const int NT = N_EDGES / 8;                 // 200000
    if (t >= NT) return;

    const int4* r4 = (const int4*)row_index;
    int4 a = __ldg(&r4[2 * t]);
    int4 b = __ldg(&r4[2 * t + 1]);

    int prev = (t == 0) ? -1 : __ldg(&row_index[8 * t - 1]);
    const bool tail = (t == NT - 1);

    if (b.w == prev && !tail) return;   // no boundary in this window

    int vals[8] = {a.x, a.y, a.z, a.w, b.x, b.y, b.z, b.w};
    const int ebase = 8 * t;
#pragma unroll
    for (int i = 0; i < 8; i++) {
        int cur = vals[i];
        if (cur != prev) {
            for (int n = prev + 1; n <= cur; n++) g_row_ptr[n] = ebase + i;
            prev = cur;
        }
    }
    if (tail) {
        for (int n = prev + 1; n <= N_NODES; n++) g_row_ptr[n] = N_EDGES;
    }
}

// ---------------------------------------------------------------------------
// Kernel 2: segment sum of gathered x rows -> g_agg.
// 16 lanes per node (float4 per lane), 2 nodes/warp, no atomics.
// ---------------------------------------------------------------------------
__global__ __launch_bounds__(256) void agg_kernel(const int* __restrict__ column_index,
                                                  const float* __restrict__ x) {
    const int warp = (blockIdx.x * blockDim.x + threadIdx.x) >> 5;
    const int lane = threadIdx.x & 31;
    const int half = lane >> 4;
    const int hl = lane & 15;
    const int node = warp * 2 + half;
    if (node >= N_NODES) return;

    const int start = g_row_ptr[node];
    const int end = g_row_ptr[node + 1];

    float ax = 0.f, ay = 0.f, az = 0.f, aw = 0.f;

    int e = start;
    for (; e + 3 < end; e += 4) {
        int s0 = __ldg(&column_index[e]);
        int s1 = __ldg(&column_index[e + 1]);
        int s2 = __ldg(&column_index[e + 2]);
        int s3 = __ldg(&column_index[e + 3]);
        float4 v0 = __ldg((const float4*)(x + (size_t)s0 * C) + hl);
        float4 v1 = __ldg((const float4*)(x + (size_t)s1 * C) + hl);
        float4 v2 = __ldg((const float4*)(x + (size_t)s2 * C) + hl);
        float4 v3 = __ldg((const float4*)(x + (size_t)s3 * C) + hl);
        ax += (v0.x + v1.x) + (v2.x + v3.x);
        ay += (v0.y + v1.y) + (v2.y + v3.y);
        az += (v0.z + v1.z) + (v2.z + v3.z);
        aw += (v0.w + v1.w) + (v2.w + v3.w);
    }
    for (; e < end; e++) {
        int s0 = __ldg(&column_index[e]);
        float4 v0 = __ldg((const float4*)(x + (size_t)s0 * C) + hl);
        ax += v0.x; ay += v0.y; az += v0.z; aw += v0.w;
    }

    ((float4*)(g_agg + (size_t)node * C))[hl] = make_float4(ax, ay, az, aw);
}

// ---------------------------------------------------------------------------
// Kernel 3: out = (g_agg @ W) * deg[row] + bias   (GEMM + fused epilogue)
// 128 rows/block, 128 threads, 32 packed f32x2 accumulators per thread.
// ---------------------------------------------------------------------------
__global__ __launch_bounds__(128) void gemm_kernel(const float* __restrict__ w,
                                                   const float* __restrict__ bias,
                                                   const float* __restrict__ degrees,
                                                   float* __restrict__ out) {
    __shared__ float ws[64 * 64];    // 16 KB, W row-major [k][n]
    __shared__ float xs[128 * 64];   // 32 KB, XOR-swizzled agg tile

    const int tid = threadIdx.x;
    const int w_id = tid >> 5;
    const int l = tid & 31;
    const long row0 = (long)blockIdx.x * 128;

    const float4* w4 = (const float4*)w;
    float4* ws4 = (float4*)ws;
#pragma unroll
    for (int i = 0; i < 8; i++) ws4[tid + i * 128] = w4[tid + i * 128];

#pragma unroll
    for (int i = 0; i < 16; i++) {
        int f4 = i * 128 + tid;
        int r = f4 >> 4, c4 = f4 & 15;
        long gr = row0 + r;
        float4 v = make_float4(0.f, 0.f, 0.f, 0.f);
        if (gr < N_NODES) v = ((const float4*)g_agg)[gr * 16 + c4];
        int sw = r & 31;
        float* base = xs + r * 64;
        base[(c4 * 4 + 0) ^ sw] = v.x;
        base[(c4 * 4 + 1) ^ sw] = v.y;
        base[(c4 * 4 + 2) ^ sw] = v.z;
        base[(c4 * 4 + 3) ^ sw] = v.w;
    }
    __syncthreads();

    unsigned long long acc[4][8];
#pragma unroll
    for (int m = 0; m < 4; m++)
#pragma unroll
        for (int j = 0; j < 8; j++) acc[m][j] = 0ull;

#pragma unroll 4
    for (int k = 0; k < 64; k++) {
        unsigned long long x2[4];
#pragma unroll
        for (int m = 0; m < 4; m++)
            x2[m] = dup_f32x2(xs[(m * 32 + l) * 64 + (k ^ l)]);

        const ulonglong2* wr = (const ulonglong2*)(ws + k * 64 + w_id * 16);
        ulonglong2 wv0 = wr[0], wv1 = wr[1], wv2 = wr[2], wv3 = wr[3];

#pragma unroll
        for (int m = 0; m < 4; m++) {
            FMA2(acc[m][0], x2[m], wv0.x);
            FMA2(acc[m][1], x2[m], wv0.y);
            FMA2(acc[m][2], x2[m], wv1.x);
            FMA2(acc[m][3], x2[m], wv1.y);
            FMA2(acc[m][4], x2[m], wv2.x);
            FMA2(acc[m][5], x2[m], wv2.y);
            FMA2(acc[m][6], x2[m], wv3.x);
            FMA2(acc[m][7], x2[m], wv3.y);
        }
    }

    // Fused epilogue: o = acc * deg[row] + bias[col], staged via smem.
    const float2* b2 = (const float2*)bias;
    unsigned long long breg[8];
#pragma unroll
    for (int j = 0; j < 8; j++) {
        float2 bv = __ldg(b2 + w_id * 8 + j);
        breg[j] = pack_f32x2(bv.x, bv.y);
    }

    __syncthreads();
    float4* xs4 = (float4*)xs;
#pragma unroll
    for (int m = 0; m < 4; m++) {
        int row = m * 32 + l;
        long gr = row0 + row;
        float dg = (gr < N_NODES) ? __ldg(&degrees[gr]) : 0.f;
        unsigned long long d2 = dup_f32x2(dg);
        int rsw = row & 15;
#pragma unroll
        for (int j4 = 0; j4 < 4; j4++) {
            unsigned long long o0 = breg[2 * j4];
            unsigned long long o1 = breg[2 * j4 + 1];
            FMA2(o0, acc[m][2 * j4], d2);
            FMA2(o1, acc[m][2 * j4 + 1], d2);
            float2 A = unpack_f32x2(o0);
            float2 B = unpack_f32x2(o1);
            xs4[row * 16 + ((w_id * 4 + j4) ^ rsw)] = make_float4(A.x, A.y, B.x, B.y);
        }
    }
    __syncthreads();
#pragma unroll
    for (int i = 0; i < 16; i++) {
        int f4 = i * 128 + tid;
        int row = f4 >> 4, c4 = f4 & 15;
        long gr = row0 + row;
        if (gr < N_NODES)
            ((float4*)out)[gr * 16 + c4] = xs4[row * 16 + (c4 ^ (row & 15))];
    }
}

// ---------------------------------------------------------------------------
extern "C" void kernel_launch(void* const* d_in, const int* in_sizes, int n_in,
                              void* d_out, int out_size) {
    const float* x            = (const float*)d_in[0];   // [N_NODES, 64]
    const float* weight       = (const float*)d_in[1];   // [64, 64]
    const float* bias         = (const float*)d_in[2];   // [64]
    const int*   column_index = (const int*)d_in[3];     // [N_EDGES]
    const int*   row_index    = (const int*)d_in[4];     // [N_EDGES] sorted
    const float* degrees      = (const float*)d_in[5];   // [N_NODES]
    float* out = (float*)d_out;                          // [N_NODES, 64]

    // 1) CSR row pointers: 8 edges/thread interval fill with fast-skip
    const int nt = N_EDGES / 8;
    rowptr_fill_kernel<<<(nt + 255) / 256, 256>>>(row_index);

    // 2) agg = segment_sum(x[col])  (2 nodes per warp, float4 lanes)
    const int warps = (N_NODES + 1) / 2;
    agg_kernel<<<(warps * 32 + 255) / 256, 256>>>(column_index, x);

    // 3) out = (agg @ W) * deg + bias
    gemm_kernel<<<(N_NODES + 127) / 128, 128>>>(weight, bias, degrees, out);
}